// round 10
// baseline (speedup 1.0000x reference)
#include <cuda_runtime.h>
#include <cuda_fp16.h>
#include <cstdint>

// Problem constants
#define BB 16
#define NN 16
#define HH 128
#define C2 256
#define NI 128

#define NCHUNK 8             // 4 K-chunks (of 64) x 2 layers
#define WBUF   32768         // weight buffer: 256 rows x 128 B (XOR swizzle, no pad)
#define HBUF   32768         // h tile: 64 rows x 512 B (XOR swizzle, no pad)

// Scratch (device globals: allocation-free contract)
__device__ float g_A   [BB * NI * C2];
__device__ float g_Bvt [BB * C2 * NI];
__device__ float g_part[BB * NI * 2 * C2];
__device__ __align__(16) __half g_Wh [NCHUNK * 256 * 64]; // W2|W3 fp16, chunk-major, k-perm
__device__ __align__(16) __half g_W1h[512 * 128];         // [W1L|W1R] fp16, k-perm
__device__ __align__(16) __half g_ench[BB * NI * HH];     // enc fp16, k-perm

__device__ __forceinline__ uint32_t smem_u32(const void* p) {
    return (uint32_t)__cvta_generic_to_shared(p);
}
__device__ __forceinline__ void cpa16(uint32_t dst, const void* src) {
    asm volatile("cp.async.cg.shared.global [%0], [%1], 16;" :: "r"(dst), "l"(src));
}
__device__ __forceinline__ void cpa_commit() { asm volatile("cp.async.commit_group;"); }
__device__ __forceinline__ void cpa_wait0()  { asm volatile("cp.async.wait_group 0;"); }

__device__ __forceinline__ void mma16(float* c, const uint32_t* a, const uint32_t* b) {
    asm volatile(
        "mma.sync.aligned.m16n8k16.row.col.f32.f16.f16.f32 "
        "{%0,%1,%2,%3}, {%4,%5,%6,%7}, {%8,%9}, {%0,%1,%2,%3};"
        : "+f"(c[0]), "+f"(c[1]), "+f"(c[2]), "+f"(c[3])
        : "r"(a[0]), "r"(a[1]), "r"(a[2]), "r"(a[3]), "r"(b[0]), "r"(b[1]));
}

// k-permutation within each 16-group: (2t,2t+1,2t+8,2t+9) -> contiguous (LDS.64 frags)
__device__ __forceinline__ int pg16(int c) {
    return (c & ~15) | ((c & 6) << 1) | ((c & 8) >> 2) | (c & 1);
}

// ---------------------------------------------------------------------------
// k_prep: all fp16 conversions/packings, 2 elems/thread (896 blocks).
// ---------------------------------------------------------------------------
__global__ __launch_bounds__(256) void k_prep(const float* __restrict__ enc,
                                              const float* __restrict__ W1,
                                              const float* __restrict__ W2,
                                              const float* __restrict__ W3)
{
    int tid = threadIdx.x;
    int blk = blockIdx.x;

    if (blk < 256) {
        int base = blk * 512 + tid * 2;
#pragma unroll
        for (int e = 0; e < 2; e++) {
            int idx = base + e;
            int L = idx >> 16, rem = idx & 65535;
            int o = rem >> 8, k = rem & 255;
            float v = (L ? W3 : W2)[o * C2 + k];
            int ck = (L << 2) | (k >> 6);
            int k6 = k & 63;
            int pk = (k6 & 48) | pg16(k6 & 15);
            g_Wh[ck * 16384 + o * 64 + pk] = __float2half_rn(v);
        }
    } else if (blk < 384) {
        int base = (blk - 256) * 512 + tid * 2;
#pragma unroll
        for (int e = 0; e < 2; e++) {
            int idx = base + e;
            int n = idx >> 7, k = idx & 127;
            float v = (n < 256) ? W1[n * C2 + k] : W1[(n - 256) * C2 + 128 + k];
            g_W1h[n * 128 + pg16(k)] = __float2half_rn(v);
        }
    } else {
        int base = (blk - 384) * 512 + tid * 2;
#pragma unroll
        for (int e = 0; e < 2; e++) {
            int idx = base + e;
            int v = idx >> 7, k = idx & 127;
            g_ench[v * 128 + pg16(k)] = __float2half_rn(enc[v * HH + k]);
        }
    }
}

// ---------------------------------------------------------------------------
// k_abt: layer-1 half projections on tensor cores (128 CTAs, 16 vectors each).
// ---------------------------------------------------------------------------
__global__ __launch_bounds__(256, 1) void k_abt()
{
    extern __shared__ char smem[];
    char* es = smem;                 // 4 KB enc tile
    char* wsm = smem + 4096;         // 128 KB weights
    uint32_t es_u = smem_u32(es), ws_u = smem_u32(wsm);

    int tid  = threadIdx.x;
    int lane = tid & 31;
    int wid  = tid >> 5;
    int vb   = blockIdx.x * 16;
    int b    = vb >> 7;

    {
        int v = tid >> 4, c4 = tid & 15;
        uint32_t inner = (uint32_t)((c4 * 16) ^ ((v & 3) << 5));
        cpa16(es_u + (uint32_t)v * 256 + inner, g_ench + (vb + v) * 128 + c4 * 8);
    }
#pragma unroll
    for (int r = 0; r < 32; r++) {
        int idx = tid + r * 256;
        int o = idx >> 4, c4 = idx & 15;
        uint32_t inner = (uint32_t)((c4 * 16) ^ ((o & 3) << 5));
        cpa16(ws_u + (uint32_t)o * 256 + inner, g_W1h + o * 128 + c4 * 8);
    }
    cpa_commit();
    cpa_wait0();
    __syncthreads();

    float acc[8][4];
#pragma unroll
    for (int nt = 0; nt < 8; nt++)
#pragma unroll
        for (int q = 0; q < 4; q++) acc[nt][q] = 0.f;

#pragma unroll
    for (int ks = 0; ks < 8; ks++) {
        uint32_t a[4];
        {
            int r0 = lane >> 2;
            uint32_t inner = (uint32_t)(ks * 32 + (lane & 3) * 8);
            uint2 lo = *(const uint2*)(es + r0 * 256 + (inner ^ ((r0 & 3) << 5)));
            int r8 = r0 + 8;
            uint2 hi = *(const uint2*)(es + r8 * 256 + (inner ^ ((r8 & 3) << 5)));
            a[0] = lo.x; a[2] = lo.y;
            a[1] = hi.x; a[3] = hi.y;
        }
#pragma unroll
        for (int nt = 0; nt < 8; nt++) {
            int o = wid * 64 + nt * 8 + (lane >> 2);
            uint32_t inner = (uint32_t)((ks * 32 + (lane & 3) * 8) ^ ((o & 3) << 5));
            uint2 bv = *(const uint2*)(wsm + o * 256 + inner);
            uint32_t bfr[2] = {bv.x, bv.y};
            mma16(acc[nt], a, bfr);
        }
    }

    {
        int v0 = vb + (lane >> 2);
#pragma unroll
        for (int nt = 0; nt < 8; nt++) {
            int n0 = wid * 64 + nt * 8 + 2 * (lane & 3);
#pragma unroll
            for (int q = 0; q < 4; q++) {
                int v = v0 + (q >= 2 ? 8 : 0);
                int n = n0 + (q & 1);
                float x = acc[nt][q];
                if (n < 256) g_A[v * C2 + n] = x;
                else         g_Bvt[(b * C2 + (n - 256)) * NI + (v & 127)] = x;
            }
        }
    }
}

// ---------------------------------------------------------------------------
// k_main: HYBRID dual-pipe fused 2-layer GEMM.
// Per warp: n-tiles 0..6 (56 cols) on the tensor pipe (m16n8k16 fp32-accum);
// n-tile 7 (8 cols x 32 rows) on the fma pipe via HFMA2, fp16 partials over
// 16 k folded to fp32. Lane map for fma slice: col = lane&7, rowgroup = lane>>3
// (8 lanes/phase share one h row -> broadcast LDS.128).
// ---------------------------------------------------------------------------
__global__ __launch_bounds__(256, 2) void k_main()
{
    extern __shared__ char smem[];
    char* hb = smem;                       // h tile, 32 KB
    char* wbase = smem + HBUF;             // 2 weight buffers, 64 KB
    uint32_t w_u32 = smem_u32(wbase);

    int tid  = threadIdx.x;
    int lane = tid & 31;
    int wid  = tid >> 5;
    int wy   = wid & 1;
    int wx   = wid >> 1;
    int mrow = wy * 32;
    int ncol = wx * 64;

    int blk = blockIdx.x;
    int b   = blk >> 8;
    int rem = blk & 255;
    int i   = rem >> 1;
    int jh  = rem & 1;
    int j0  = jh * 64;

    // fma-slice lane mapping
    int fcol = lane & 7;                   // column within n-tile 7
    int fgrp = lane >> 3;                  // row group (8 rows each)
    int fo   = ncol + 56 + fcol;           // output channel (W row)

    // ---- prefetch chunk 0 ----
#pragma unroll
    for (int r = 0; r < 8; r++) {
        int idx = tid + r * 256;
        int o = idx >> 3, c4 = idx & 7;
        uint32_t inner = (uint32_t)((c4 * 16) ^ ((o & 3) << 5));
        cpa16(w_u32 + (uint32_t)o * 128 + inner, g_Wh + o * 64 + c4 * 8);
    }
    cpa_commit();

    // ---- build h1 while chunk 0 flies ----
    {
        int p   = tid & 127;
        int rg  = tid >> 7;
        int c0  = 2 * p;
        float a0 = g_A[(b * NI + i) * C2 + c0];
        float a1 = g_A[(b * NI + i) * C2 + c0 + 1];
        const float* bp0 = g_Bvt + (b * C2 + c0)     * NI + j0 + rg * 32;
        const float* bp1 = g_Bvt + (b * C2 + c0 + 1) * NI + j0 + rg * 32;
        int pcb = pg16(c0) * 2;
#pragma unroll
        for (int r4 = 0; r4 < 32; r4 += 4) {
            float4 v0 = *(const float4*)(bp0 + r4);
            float4 v1 = *(const float4*)(bp1 + r4);
            int row = rg * 32 + r4;
#pragma unroll
            for (int q = 0; q < 4; q++) {
                float e0 = (q == 0 ? v0.x : q == 1 ? v0.y : q == 2 ? v0.z : v0.w);
                float e1 = (q == 0 ? v1.x : q == 1 ? v1.y : q == 2 ? v1.z : v1.w);
                __half2 hv = __floats2half2_rn(fmaxf(e0 + a0, 0.f), fmaxf(e1 + a1, 0.f));
                int rr = row + q;
                *(__half2*)(hb + rr * 512 + (pcb ^ ((rr & 3) << 5))) = hv;
            }
        }
    }

    float acc[2][7][4];                    // tensor-path accumulators (n-tiles 0..6)
#pragma unroll
    for (int mt = 0; mt < 2; mt++)
#pragma unroll
        for (int nt = 0; nt < 7; nt++)
#pragma unroll
            for (int q = 0; q < 4; q++) acc[mt][nt][q] = 0.f;

    float facc[8];                         // fma-path accumulators (8 rows x 1 col)
#pragma unroll
    for (int r = 0; r < 8; r++) facc[r] = 0.f;

    for (int ck = 0; ck < NCHUNK; ck++) {
        cpa_wait0();
        __syncthreads();

        if (ck < NCHUNK - 1) {             // prefetch ck+1 into the other buffer
            const __half* src = g_Wh + (ck + 1) * 16384;
            uint32_t dbase = w_u32 + (uint32_t)(((ck + 1) & 1) * WBUF);
#pragma unroll
            for (int r = 0; r < 8; r++) {
                int idx = tid + r * 256;
                int o = idx >> 3, c4 = idx & 7;
                uint32_t inner = (uint32_t)((c4 * 16) ^ ((o & 3) << 5));
                cpa16(dbase + (uint32_t)o * 128 + inner, src + o * 64 + c4 * 8);
            }
            cpa_commit();
        }

        char* wc  = wbase + (ck & 1) * WBUF;
        int   ckb = (ck & 3) * 128;

        // ---- tensor path: n-tiles 0..6, K=64 (4 ksteps) ----
#pragma unroll
        for (int ks = 0; ks < 4; ks++) {
            uint32_t a[2][4];
#pragma unroll
            for (int mt = 0; mt < 2; mt++) {
                int r0 = mrow + mt * 16 + (lane >> 2);
                uint32_t inner = (uint32_t)((ckb + ks * 32 + (lane & 3) * 8));
                uint2 lo = *(const uint2*)(hb + r0 * 512 + (inner ^ ((r0 & 3) << 5)));
                int r8 = r0 + 8;
                uint2 hi = *(const uint2*)(hb + r8 * 512 + (inner ^ ((r8 & 3) << 5)));
                a[mt][0] = lo.x; a[mt][2] = lo.y;
                a[mt][1] = hi.x; a[mt][3] = hi.y;
            }
#pragma unroll
            for (int nt = 0; nt < 7; nt++) {
                int o = ncol + nt * 8 + (lane >> 2);
                uint32_t inner = (uint32_t)((ks * 32 + (lane & 3) * 8) ^ ((o & 3) << 5));
                uint2 bv = *(const uint2*)(wc + o * 128 + inner);
                uint32_t bfr[2] = {bv.x, bv.y};
                mma16(acc[0][nt], a[0], bfr);
                mma16(acc[1][nt], a[1], bfr);
            }
        }

        // ---- fma path: n-tile 7 (8 cols x 32 rows) via HFMA2 ----
        {
            uint32_t wswz = (uint32_t)((fo & 3) << 5);
#pragma unroll
            for (int kg = 0; kg < 4; kg++) {       // 16-k fold groups
                __half2 p[8];
#pragma unroll
                for (int r = 0; r < 8; r++) p[r] = __floats2half2_rn(0.f, 0.f);
#pragma unroll
                for (int u = 0; u < 2; u++) {
                    uint4 w4 = *(const uint4*)(wc + fo * 128 +
                                  ((uint32_t)(kg * 32 + u * 16) ^ wswz));
#pragma unroll
                    for (int r = 0; r < 8; r++) {
                        int row = mrow + fgrp * 8 + r;
                        uint4 h4 = *(const uint4*)(hb + row * 512 +
                                      ((uint32_t)(ckb + kg * 32 + u * 16)
                                       ^ ((row & 3) << 5)));
                        p[r] = __hfma2(*(__half2*)&h4.x, *(__half2*)&w4.x, p[r]);
                        p[r] = __hfma2(*(__half2*)&h4.y, *(__half2*)&w4.y, p[r]);
                        p[r] = __hfma2(*(__half2*)&h4.z, *(__half2*)&w4.z, p[r]);
                        p[r] = __hfma2(*(__half2*)&h4.w, *(__half2*)&w4.w, p[r]);
                    }
                }
#pragma unroll
                for (int r = 0; r < 8; r++) {      // fp32 fold every 16 k
                    float2 f = __half22float2(p[r]);
                    facc[r] += f.x + f.y;
                }
            }
        }

        if (ck == 3) {
            // layer boundary: write h2 for all 256 cols, reset accumulators
            __syncthreads();
#pragma unroll
            for (int mt = 0; mt < 2; mt++) {
                int r = mrow + mt * 16 + (lane >> 2);
#pragma unroll
                for (int nt = 0; nt < 7; nt++) {
                    int c0 = ncol + nt * 8 + 2 * (lane & 3);
                    int pcb = pg16(c0) * 2;
                    __half2 v01 = __floats2half2_rn(fmaxf(acc[mt][nt][0], 0.f),
                                                    fmaxf(acc[mt][nt][1], 0.f));
                    __half2 v23 = __floats2half2_rn(fmaxf(acc[mt][nt][2], 0.f),
                                                    fmaxf(acc[mt][nt][3], 0.f));
                    int r8 = r + 8;
                    *(__half2*)(hb + r * 512 + (pcb ^ ((r & 3) << 5)))   = v01;
                    *(__half2*)(hb + r8 * 512 + (pcb ^ ((r8 & 3) << 5))) = v23;
#pragma unroll
                    for (int q = 0; q < 4; q++) acc[mt][nt][q] = 0.f;
                }
            }
            {
                int pcb = pg16(fo - ncol + ncol) * 2;   // = pg16(fo)*2
#pragma unroll
                for (int r = 0; r < 8; r++) {
                    int row = mrow + fgrp * 8 + r;
                    *(__half*)(hb + row * 512 + (pcb ^ ((row & 3) << 5))) =
                        __float2half_rn(fmaxf(facc[r], 0.f));
                    facc[r] = 0.f;
                }
            }
            // next iteration's top __syncthreads orders writes before reads
        }
    }

    // ---- epilogue: relu + deterministic sum over the CTA's 64 rows ----
    __syncthreads();
    float* red = (float*)wbase;            // [2][256]
#pragma unroll
    for (int nt = 0; nt < 7; nt++) {
        float ev = 0.f, od = 0.f;
#pragma unroll
        for (int mt = 0; mt < 2; mt++) {
            ev += fmaxf(acc[mt][nt][0], 0.f) + fmaxf(acc[mt][nt][2], 0.f);
            od += fmaxf(acc[mt][nt][1], 0.f) + fmaxf(acc[mt][nt][3], 0.f);
        }
#pragma unroll
        for (int o = 4; o <= 16; o <<= 1) {
            ev += __shfl_xor_sync(0xffffffffu, ev, o);
            od += __shfl_xor_sync(0xffffffffu, od, o);
        }
        if (lane < 4) {
            red[wy * C2 + ncol + nt * 8 + 2 * lane]     = ev;
            red[wy * C2 + ncol + nt * 8 + 2 * lane + 1] = od;
        }
    }
    {   // fma slice: sum 8 rows per lane, then across the 4 row groups
        float s = 0.f;
#pragma unroll
        for (int r = 0; r < 8; r++) s += fmaxf(facc[r], 0.f);
        s += __shfl_xor_sync(0xffffffffu, s, 8);
        s += __shfl_xor_sync(0xffffffffu, s, 16);
        if (lane < 8) red[wy * C2 + ncol + 56 + lane] = s;
    }
    __syncthreads();
    g_part[((b * NI + i) * 2 + jh) * C2 + tid] = red[tid] + red[C2 + tid];
}

// ---------------------------------------------------------------------------
__global__ __launch_bounds__(512) void k_fin(float* __restrict__ out)
{
    int idx = blockIdx.x * 512 + threadIdx.x;
    int c = idx & 255, bn = idx >> 8;
    int b = bn >> 4, n1 = bn & 15;
    float sum = 0.f;
#pragma unroll
    for (int k1 = 0; k1 < 8; k1++)
#pragma unroll
        for (int jhv = 0; jhv < 2; jhv++)
            sum += g_part[((b * NI + n1 * 8 + k1) * 2 + jhv) * C2 + c];
    out[idx] = sum * (1.0f / 1024.0f);
}

// ---------------------------------------------------------------------------
extern "C" void kernel_launch(void* const* d_in, const int* in_sizes, int n_in,
                              void* d_out, int out_size)
{
    const float* enc = (const float*)d_in[0];
    const float* W1  = (const float*)d_in[1];
    const float* W2  = (const float*)d_in[2];
    const float* W3  = (const float*)d_in[3];
    float* out       = (float*)d_out;

    const int smem_main = HBUF + 2 * WBUF;   // 98304
    const int smem_abt  = 4096 + 512 * 256;  // 135168
    cudaFuncSetAttribute(k_main, cudaFuncAttributeMaxDynamicSharedMemorySize, smem_main);
    cudaFuncSetAttribute(k_abt,  cudaFuncAttributeMaxDynamicSharedMemorySize, smem_abt);

    k_prep<<<896, 256>>>(enc, W1, W2, W3);
    k_abt <<<BB * NI / 16, 256, smem_abt>>>();
    k_main<<<BB * NI * 2, 256, smem_main>>>();
    k_fin <<<(BB * NN * C2) / 512, 512>>>(out);
}

// round 11
// speedup vs baseline: 1.8508x; 1.8508x over previous
#include <cuda_runtime.h>
#include <cuda_fp16.h>
#include <cstdint>

// Problem constants
#define BB 16
#define NN 16
#define HH 128
#define C2 256
#define NI 128

#define NCHUNK 8             // 4 K-chunks (of 64) x 2 layers
#define WBUF   32768         // weight buffer: 256 rows x 128 B (XOR swizzle, no pad)
#define HBUF   32768         // h tile: 64 rows x 512 B (XOR swizzle, no pad)

// Scratch (device globals: allocation-free contract)
__device__ float g_A   [BB * NI * C2];
__device__ float g_Bvt [BB * C2 * NI];
__device__ float g_part[BB * NI * 2 * C2];
__device__ __align__(16) __half g_Wh [NCHUNK * 256 * 64]; // W2|W3 fp16, chunk-major, k-perm
__device__ __align__(16) __half g_W1h[512 * 128];         // [W1L|W1R] fp16, k-perm
__device__ __align__(16) __half g_ench[BB * NI * HH];     // enc fp16, k-perm

__device__ __forceinline__ uint32_t smem_u32(const void* p) {
    return (uint32_t)__cvta_generic_to_shared(p);
}
__device__ __forceinline__ void cpa16(uint32_t dst, const void* src) {
    asm volatile("cp.async.cg.shared.global [%0], [%1], 16;" :: "r"(dst), "l"(src));
}
__device__ __forceinline__ void cpa_commit() { asm volatile("cp.async.commit_group;"); }
__device__ __forceinline__ void cpa_wait0()  { asm volatile("cp.async.wait_group 0;"); }

__device__ __forceinline__ void mma16(float* c, const uint32_t* a, const uint32_t* b) {
    asm volatile(
        "mma.sync.aligned.m16n8k16.row.col.f32.f16.f16.f32 "
        "{%0,%1,%2,%3}, {%4,%5,%6,%7}, {%8,%9}, {%0,%1,%2,%3};"
        : "+f"(c[0]), "+f"(c[1]), "+f"(c[2]), "+f"(c[3])
        : "r"(a[0]), "r"(a[1]), "r"(a[2]), "r"(a[3]), "r"(b[0]), "r"(b[1]));
}

// k-permutation within each 16-group: (2t,2t+1,2t+8,2t+9) -> contiguous (LDS.64 frags)
__device__ __forceinline__ int pg16(int c) {
    return (c & ~15) | ((c & 6) << 1) | ((c & 8) >> 2) | (c & 1);
}

// ---------------------------------------------------------------------------
// k_prep: all fp16 conversions/packings, 2 elems/thread (896 blocks).
//  blocks [0,256):    W2|W3 -> g_Wh   (chunk-major, k-permuted)
//  blocks [256,384):  [W1L|W1R] -> g_W1h[n][k]
//  blocks [384,896):  enc -> g_ench (k-permuted)
// ---------------------------------------------------------------------------
__global__ __launch_bounds__(256) void k_prep(const float* __restrict__ enc,
                                              const float* __restrict__ W1,
                                              const float* __restrict__ W2,
                                              const float* __restrict__ W3)
{
    int tid = threadIdx.x;
    int blk = blockIdx.x;

    if (blk < 256) {
        int base = blk * 512 + tid * 2;              // 2 consecutive k per thread
#pragma unroll
        for (int e = 0; e < 2; e++) {
            int idx = base + e;                      // 131072 total
            int L = idx >> 16, rem = idx & 65535;
            int o = rem >> 8, k = rem & 255;
            float v = (L ? W3 : W2)[o * C2 + k];
            int ck = (L << 2) | (k >> 6);
            int k6 = k & 63;
            int pk = (k6 & 48) | pg16(k6 & 15);
            g_Wh[ck * 16384 + o * 64 + pk] = __float2half_rn(v);
        }
    } else if (blk < 384) {
        int base = (blk - 256) * 512 + tid * 2;      // 65536 total
#pragma unroll
        for (int e = 0; e < 2; e++) {
            int idx = base + e;
            int n = idx >> 7, k = idx & 127;
            float v = (n < 256) ? W1[n * C2 + k] : W1[(n - 256) * C2 + 128 + k];
            g_W1h[n * 128 + pg16(k)] = __float2half_rn(v);
        }
    } else {
        int base = (blk - 384) * 512 + tid * 2;      // 262144 total
#pragma unroll
        for (int e = 0; e < 2; e++) {
            int idx = base + e;
            int v = idx >> 7, k = idx & 127;
            g_ench[v * 128 + pg16(k)] = __float2half_rn(enc[v * HH + k]);
        }
    }
}

// ---------------------------------------------------------------------------
// k_abt: layer-1 half projections on tensor cores, full-chip width.
// CTA = 16 vectors x 512 outputs; 128 CTAs, 256 threads (8 warps, tile 16x64).
// smem: enc tile 16x256B (4 KB) + W 512x256B (128 KB), XOR-swizzled.
// ---------------------------------------------------------------------------
__global__ __launch_bounds__(256, 1) void k_abt()
{
    extern __shared__ char smem[];
    char* es = smem;                 // 4 KB enc tile
    char* wsm = smem + 4096;         // 128 KB weights
    uint32_t es_u = smem_u32(es), ws_u = smem_u32(wsm);

    int tid  = threadIdx.x;
    int lane = tid & 31;
    int wid  = tid >> 5;
    int vb   = blockIdx.x * 16;
    int b    = vb >> 7;

    // enc tile: 256 x 16B chunks -> 1 per thread
    {
        int v = tid >> 4, c4 = tid & 15;
        uint32_t inner = (uint32_t)((c4 * 16) ^ ((v & 3) << 5));
        cpa16(es_u + (uint32_t)v * 256 + inner, g_ench + (vb + v) * 128 + c4 * 8);
    }
    // W tile: 8192 x 16B chunks -> 32 per thread
#pragma unroll
    for (int r = 0; r < 32; r++) {
        int idx = tid + r * 256;
        int o = idx >> 4, c4 = idx & 15;
        uint32_t inner = (uint32_t)((c4 * 16) ^ ((o & 3) << 5));
        cpa16(ws_u + (uint32_t)o * 256 + inner, g_W1h + o * 128 + c4 * 8);
    }
    cpa_commit();
    cpa_wait0();
    __syncthreads();

    float acc[8][4];
#pragma unroll
    for (int nt = 0; nt < 8; nt++)
#pragma unroll
        for (int q = 0; q < 4; q++) acc[nt][q] = 0.f;

#pragma unroll
    for (int ks = 0; ks < 8; ks++) {
        uint32_t a[4];
        {
            int r0 = lane >> 2;
            uint32_t inner = (uint32_t)(ks * 32 + (lane & 3) * 8);
            uint2 lo = *(const uint2*)(es + r0 * 256 + (inner ^ ((r0 & 3) << 5)));
            int r8 = r0 + 8;
            uint2 hi = *(const uint2*)(es + r8 * 256 + (inner ^ ((r8 & 3) << 5)));
            a[0] = lo.x; a[2] = lo.y;
            a[1] = hi.x; a[3] = hi.y;
        }
#pragma unroll
        for (int nt = 0; nt < 8; nt++) {
            int o = wid * 64 + nt * 8 + (lane >> 2);
            uint32_t inner = (uint32_t)((ks * 32 + (lane & 3) * 8) ^ ((o & 3) << 5));
            uint2 bv = *(const uint2*)(wsm + o * 256 + inner);
            uint32_t bfr[2] = {bv.x, bv.y};
            mma16(acc[nt], a, bfr);
        }
    }

    // write out: n<256 -> g_A[v][n]; n>=256 -> g_Bvt[b][n-256][v&127]
    {
        int v0 = vb + (lane >> 2);
#pragma unroll
        for (int nt = 0; nt < 8; nt++) {
            int n0 = wid * 64 + nt * 8 + 2 * (lane & 3);
#pragma unroll
            for (int q = 0; q < 4; q++) {
                int v = v0 + (q >= 2 ? 8 : 0);
                int n = n0 + (q & 1);
                float x = acc[nt][q];
                if (n < 256) g_A[v * C2 + n] = x;
                else         g_Bvt[(b * C2 + (n - 256)) * NI + (v & 127)] = x;
            }
        }
    }
}

// ---------------------------------------------------------------------------
// k_main: fused 2-layer GEMM, fp16 m16n8k16 (fp32 accum), 2 CTAs/SM.
// AT the legacy-tensor HW floor (512 MAC/cyc/SM) — unchanged champion.
// ---------------------------------------------------------------------------
__global__ __launch_bounds__(256, 2) void k_main()
{
    extern __shared__ char smem[];
    char* hb = smem;                       // h tile, 32 KB
    char* wbase = smem + HBUF;             // 2 weight buffers, 64 KB
    uint32_t w_u32 = smem_u32(wbase);

    int tid  = threadIdx.x;
    int lane = tid & 31;
    int wid  = tid >> 5;
    int wy   = wid & 1;
    int wx   = wid >> 1;
    int mrow = wy * 32;
    int ncol = wx * 64;

    int blk = blockIdx.x;
    int b   = blk >> 8;
    int rem = blk & 255;
    int i   = rem >> 1;
    int jh  = rem & 1;
    int j0  = jh * 64;

    // ---- prefetch chunk 0 ----
#pragma unroll
    for (int r = 0; r < 8; r++) {
        int idx = tid + r * 256;
        int o = idx >> 3, c4 = idx & 7;
        uint32_t inner = (uint32_t)((c4 * 16) ^ ((o & 3) << 5));
        cpa16(w_u32 + (uint32_t)o * 128 + inner, g_Wh + o * 64 + c4 * 8);
    }
    cpa_commit();

    // ---- build h1 while chunk 0 flies ----
    {
        int p   = tid & 127;
        int rg  = tid >> 7;
        int c0  = 2 * p;
        float a0 = g_A[(b * NI + i) * C2 + c0];
        float a1 = g_A[(b * NI + i) * C2 + c0 + 1];
        const float* bp0 = g_Bvt + (b * C2 + c0)     * NI + j0 + rg * 32;
        const float* bp1 = g_Bvt + (b * C2 + c0 + 1) * NI + j0 + rg * 32;
        int pcb = pg16(c0) * 2;
#pragma unroll
        for (int r4 = 0; r4 < 32; r4 += 4) {
            float4 v0 = *(const float4*)(bp0 + r4);
            float4 v1 = *(const float4*)(bp1 + r4);
            int row = rg * 32 + r4;
#pragma unroll
            for (int q = 0; q < 4; q++) {
                float e0 = (q == 0 ? v0.x : q == 1 ? v0.y : q == 2 ? v0.z : v0.w);
                float e1 = (q == 0 ? v1.x : q == 1 ? v1.y : q == 2 ? v1.z : v1.w);
                __half2 hv = __floats2half2_rn(fmaxf(e0 + a0, 0.f), fmaxf(e1 + a1, 0.f));
                int rr = row + q;
                *(__half2*)(hb + rr * 512 + (pcb ^ ((rr & 3) << 5))) = hv;
            }
        }
    }

    float acc[2][8][4];
#pragma unroll
    for (int mt = 0; mt < 2; mt++)
#pragma unroll
        for (int nt = 0; nt < 8; nt++)
#pragma unroll
            for (int q = 0; q < 4; q++) acc[mt][nt][q] = 0.f;

    for (int ck = 0; ck < NCHUNK; ck++) {
        cpa_wait0();
        __syncthreads();

        if (ck < NCHUNK - 1) {             // prefetch ck+1 into the other buffer
            const __half* src = g_Wh + (ck + 1) * 16384;
            uint32_t dbase = w_u32 + (uint32_t)(((ck + 1) & 1) * WBUF);
#pragma unroll
            for (int r = 0; r < 8; r++) {
                int idx = tid + r * 256;
                int o = idx >> 3, c4 = idx & 7;
                uint32_t inner = (uint32_t)((c4 * 16) ^ ((o & 3) << 5));
                cpa16(dbase + (uint32_t)o * 128 + inner, src + o * 64 + c4 * 8);
            }
            cpa_commit();
        }

        // ---- compute chunk ck (K=64 -> 4 ksteps of 16) ----
        char* wc  = wbase + (ck & 1) * WBUF;
        int   ckb = (ck & 3) * 128;
#pragma unroll
        for (int ks = 0; ks < 4; ks++) {
            uint32_t a[2][4];
#pragma unroll
            for (int mt = 0; mt < 2; mt++) {
                int r0 = mrow + mt * 16 + (lane >> 2);
                uint32_t inner = (uint32_t)((ckb + ks * 32 + (lane & 3) * 8));
                uint2 lo = *(const uint2*)(hb + r0 * 512 + (inner ^ ((r0 & 3) << 5)));
                int r8 = r0 + 8;
                uint2 hi = *(const uint2*)(hb + r8 * 512 + (inner ^ ((r8 & 3) << 5)));
                a[mt][0] = lo.x; a[mt][2] = lo.y;
                a[mt][1] = hi.x; a[mt][3] = hi.y;
            }
#pragma unroll
            for (int nt = 0; nt < 8; nt++) {
                int o = ncol + nt * 8 + (lane >> 2);
                uint32_t inner = (uint32_t)((ks * 32 + (lane & 3) * 8) ^ ((o & 3) << 5));
                uint2 bv = *(const uint2*)(wc + o * 128 + inner);
                uint32_t bfr[2] = {bv.x, bv.y};
                mma16(acc[0][nt], a[0], bfr);
                mma16(acc[1][nt], a[1], bfr);
            }
        }

        if (ck == 3) {
            // layer boundary: overwrite h with h2 (same permuted+swizzled layout)
            __syncthreads();
#pragma unroll
            for (int mt = 0; mt < 2; mt++) {
                int r = mrow + mt * 16 + (lane >> 2);
#pragma unroll
                for (int nt = 0; nt < 8; nt++) {
                    int c0 = ncol + nt * 8 + 2 * (lane & 3);
                    int pcb = pg16(c0) * 2;
                    __half2 v01 = __floats2half2_rn(fmaxf(acc[mt][nt][0], 0.f),
                                                    fmaxf(acc[mt][nt][1], 0.f));
                    __half2 v23 = __floats2half2_rn(fmaxf(acc[mt][nt][2], 0.f),
                                                    fmaxf(acc[mt][nt][3], 0.f));
                    int r8 = r + 8;
                    *(__half2*)(hb + r * 512 + (pcb ^ ((r & 3) << 5)))   = v01;
                    *(__half2*)(hb + r8 * 512 + (pcb ^ ((r8 & 3) << 5))) = v23;
#pragma unroll
                    for (int q = 0; q < 4; q++) acc[mt][nt][q] = 0.f;
                }
            }
        }
    }

    // ---- epilogue: relu + deterministic sum over the CTA's 64 rows ----
    __syncthreads();
    float* red = (float*)wbase;            // [2][256]
#pragma unroll
    for (int nt = 0; nt < 8; nt++) {
        float ev = 0.f, od = 0.f;
#pragma unroll
        for (int mt = 0; mt < 2; mt++) {
            ev += fmaxf(acc[mt][nt][0], 0.f) + fmaxf(acc[mt][nt][2], 0.f);
            od += fmaxf(acc[mt][nt][1], 0.f) + fmaxf(acc[mt][nt][3], 0.f);
        }
#pragma unroll
        for (int o = 4; o <= 16; o <<= 1) {
            ev += __shfl_xor_sync(0xffffffffu, ev, o);
            od += __shfl_xor_sync(0xffffffffu, od, o);
        }
        if (lane < 4) {
            red[wy * C2 + ncol + nt * 8 + 2 * lane]     = ev;
            red[wy * C2 + ncol + nt * 8 + 2 * lane + 1] = od;
        }
    }
    __syncthreads();
    g_part[((b * NI + i) * 2 + jh) * C2 + tid] = red[tid] + red[C2 + tid];
}

// ---------------------------------------------------------------------------
__global__ __launch_bounds__(512) void k_fin(float* __restrict__ out)
{
    int idx = blockIdx.x * 512 + threadIdx.x;
    int c = idx & 255, bn = idx >> 8;
    int b = bn >> 4, n1 = bn & 15;
    float sum = 0.f;
#pragma unroll
    for (int k1 = 0; k1 < 8; k1++)
#pragma unroll
        for (int jhv = 0; jhv < 2; jhv++)
            sum += g_part[((b * NI + n1 * 8 + k1) * 2 + jhv) * C2 + c];
    out[idx] = sum * (1.0f / 1024.0f);
}

// ---------------------------------------------------------------------------
extern "C" void kernel_launch(void* const* d_in, const int* in_sizes, int n_in,
                              void* d_out, int out_size)
{
    const float* enc = (const float*)d_in[0];
    const float* W1  = (const float*)d_in[1];
    const float* W2  = (const float*)d_in[2];
    const float* W3  = (const float*)d_in[3];
    float* out       = (float*)d_out;

    const int smem_main = HBUF + 2 * WBUF;   // 98304
    const int smem_abt  = 4096 + 512 * 256;  // 135168
    cudaFuncSetAttribute(k_main, cudaFuncAttributeMaxDynamicSharedMemorySize, smem_main);
    cudaFuncSetAttribute(k_abt,  cudaFuncAttributeMaxDynamicSharedMemorySize, smem_abt);

    k_prep<<<896, 256>>>(enc, W1, W2, W3);
    k_abt <<<BB * NI / 16, 256, smem_abt>>>();
    k_main<<<BB * NI * 2, 256, smem_main>>>();
    k_fin <<<(BB * NN * C2) / 512, 512>>>(out);
}